// round 15
// baseline (speedup 1.0000x reference)
#include <cuda_runtime.h>
#include <cuda_fp16.h>
#include <math.h>
#include <stdint.h>

#define MAXN     50000
#define MAXE     1600000
#define IN_DIM   1024
#define HID      128
#define MAXG     64
#define MAXETOT  (MAXE + MAXN)

// fp16 mma GEMM config: 256 threads, 8 warps (4m x 2n), warp tile 32x64, BK=32
#define NCH      (IN_DIM / 32)      // 32 chunks of k=32
#define A_ROWB   80                 // bytes per A smem row (64 used + 16 pad)
#define A_STG    (128 * A_ROWB)     // 10240 per stage
#define B_ROWB   80                 // bytes per B col-row (64 used + 16 pad)
#define B_STG    (128 * B_ROWB)     // 10240 per stage
#define SM_B0    (2 * A_STG)
#define SM_TOT   (2 * A_STG + 2 * B_STG)   // 40960 bytes

// ---------------- device scratch (static; no allocations) ----------------
__device__ __half g_hh[(size_t)MAXN * HID];   // h in fp16 (gather copy)
__device__ __half2 g_Wp2[NCH * 2048];         // W col-major per chunk: [ch][n][kpair]
__device__ int    g_csr[MAXETOT];             // src ids grouped by dst
__device__ float  g_asrc[MAXN];
__device__ float  g_adst[MAXN];
__device__ int    g_cnt[MAXN];                // per-dst in-degree (re-zeroed by scan1)
__device__ int    g_off[MAXN + 1];            // CSR offsets
__device__ int    g_cur[MAXN];                // scatter cursors
__device__ int    g_bsum[256];                // scan block sums

// ---------------- kernels ----------------

// prepW: pool=0 + W -> half2, col-major per chunk: [ch][n][kpair 0..15].
__global__ void prepW_kernel(const float* __restrict__ W, float* pool) {
    int i = blockIdx.x * blockDim.x + threadIdx.x;
    if (i < MAXG * HID) pool[i] = 0.f;
    if (i < NCH * 2048) {
        int kp = i & 15;
        int n  = (i >> 4) & 127;
        int ch = i >> 11;
        int k0 = ch * 32 + kp * 2;
        g_Wp2[i] = __floats2half2_rn(W[(size_t)k0 * HID + n],
                                     W[(size_t)(k0 + 1) * HID + n]);
    }
}

// count: per-dst edge count (independent of W; runs on the CSR branch).
__global__ void count_kernel(const int* __restrict__ ei, int E) {
    int i = blockIdx.x * blockDim.x + threadIdx.x;
    if (i < E) atomicAdd(&g_cnt[ei[E + i]], 1);
}

#define LDSM_X4(r0_, r1_, r2_, r3_, addr_) \
    asm volatile("ldmatrix.sync.aligned.m8n8.x4.shared.b16 {%0,%1,%2,%3}, [%4];" \
                 : "=r"(r0_), "=r"(r1_), "=r"(r2_), "=r"(r3_) : "r"(addr_))

// fp16 mma.sync m16n8k16 GEMM with fused attdot epilogue. h written fp16.
// 256 threads, 8 warps (warp&3 = m quarter, warp>>2 = n half), BK=32, 2-stage.
// Fragment loads via ldmatrix.x4. DRAM-bound on the A read (~80us floor).
__global__ __launch_bounds__(256) void gemm_f16_kernel(
        const float* __restrict__ A,
        const float* __restrict__ att_src,
        const float* __restrict__ att_dst, int M) {
    __shared__ char smem[SM_TOT];
    const uint32_t sbase = (uint32_t)__cvta_generic_to_shared(smem);

    const int tid  = threadIdx.x;
    const int lane = tid & 31;
    const int warp = tid >> 5;
    const int gid  = lane >> 2;   // 0..7
    const int tig  = lane & 3;    // 0..3
    const int wm   = (warp & 3) * 32;
    const int wn   = (warp >> 2) * 64;
    const int block_row = blockIdx.x * 128;

    // ldmatrix per-lane base addresses.
    uint32_t aLm[2];
#pragma unroll
    for (int mt = 0; mt < 2; mt++) {
        int row = wm + mt * 16 + (lane & 7) + (((lane >> 3) & 1) << 3);
        aLm[mt] = sbase + row * A_ROWB + (((lane >> 4) & 1) << 4);
    }
    uint32_t bLm[4];
#pragma unroll
    for (int ntp = 0; ntp < 4; ntp++) {
        int col = wn + ntp * 16 + (lane & 7) + (((lane >> 4) & 1) << 3);
        bLm[ntp] = sbase + SM_B0 + col * B_ROWB + (((lane >> 3) & 1) << 4);
    }

    // A LDG mapping: iter i: row = i*32 + (tid>>3), cols (tid&7)*4 (float4)
    const int ar = tid >> 3;   // 0..31
    const int aq = tid & 7;    // 0..7
    bool avalid[4];
    const float* aptr[4];
#pragma unroll
    for (int i = 0; i < 4; i++) {
        int gr = block_row + i * 32 + ar;
        avalid[i] = gr < M;
        aptr[i] = A + (size_t)(avalid[i] ? gr : 0) * IN_DIM + aq * 4;
    }

    float4 areg[4];
#define LDA(c_) do {                                                         \
    _Pragma("unroll")                                                        \
    for (int i = 0; i < 4; i++)                                              \
        areg[i] = avalid[i] ? *(const float4*)(aptr[i] + (c_) * 32)          \
                            : make_float4(0.f, 0.f, 0.f, 0.f);               \
} while (0)
#define STA(buf_) do {                                                       \
    _Pragma("unroll")                                                        \
    for (int i = 0; i < 4; i++) {                                            \
        __half2 h0 = __floats2half2_rn(areg[i].x, areg[i].y);                \
        __half2 h1 = __floats2half2_rn(areg[i].z, areg[i].w);                \
        uint2 u; u.x = *(uint32_t*)&h0; u.y = *(uint32_t*)&h1;               \
        *(uint2*)(smem + (buf_) * A_STG + (i * 32 + ar) * A_ROWB + aq * 8) = u; \
    }                                                                        \
} while (0)
#define LDB(c_, buf_) do {                                                   \
    _Pragma("unroll")                                                        \
    for (int j = 0; j < 2; j++) {                                            \
        int q = j * 256 + tid;                                               \
        const __half2* src = g_Wp2 + (size_t)(c_) * 2048 + q * 4;            \
        uint32_t dst = sbase + SM_B0 + (buf_) * B_STG +                      \
                       (q >> 2) * B_ROWB + (q & 3) * 16;                     \
        asm volatile("cp.async.cg.shared.global [%0], [%1], 16;"             \
                     :: "r"(dst), "l"(src));                                 \
    }                                                                        \
    asm volatile("cp.async.commit_group;");                                  \
} while (0)

    float acc[2][8][4];
#pragma unroll
    for (int mt = 0; mt < 2; mt++)
#pragma unroll
        for (int nt = 0; nt < 8; nt++)
#pragma unroll
            for (int i = 0; i < 4; i++) acc[mt][nt][i] = 0.f;

    // prologue
    LDA(0); STA(0); LDB(0, 0);

#pragma unroll 1
    for (int c = 0; c < NCH; c++) {
        const int buf = c & 1;
        if (c < NCH - 1) LDA(c + 1);          // A global->reg prefetch
        asm volatile("cp.async.wait_group 0;");   // B(c) ready
        __syncthreads();
        if (c < NCH - 1) LDB(c + 1, buf ^ 1); // hide B latency under compute

        const uint32_t aOff = buf * A_STG;
        const uint32_t bOff = buf * B_STG;
#pragma unroll
        for (int ks = 0; ks < 2; ks++) {
            uint32_t afr[2][4];
#pragma unroll
            for (int mt = 0; mt < 2; mt++)
                LDSM_X4(afr[mt][0], afr[mt][1], afr[mt][2], afr[mt][3],
                        aLm[mt] + aOff + ks * 32);
            uint32_t bfr[8][2];
#pragma unroll
            for (int ntp = 0; ntp < 4; ntp++)
                LDSM_X4(bfr[2 * ntp][0], bfr[2 * ntp][1],
                        bfr[2 * ntp + 1][0], bfr[2 * ntp + 1][1],
                        bLm[ntp] + bOff + ks * 32);
#pragma unroll
            for (int mt = 0; mt < 2; mt++)
#pragma unroll
                for (int nt = 0; nt < 8; nt++) {
                    asm("mma.sync.aligned.m16n8k16.row.col.f32.f16.f16.f32 "
                        "{%0,%1,%2,%3}, {%4,%5,%6,%7}, {%8,%9}, {%0,%1,%2,%3};"
                        : "+f"(acc[mt][nt][0]), "+f"(acc[mt][nt][1]),
                          "+f"(acc[mt][nt][2]), "+f"(acc[mt][nt][3])
                        : "r"(afr[mt][0]), "r"(afr[mt][1]),
                          "r"(afr[mt][2]), "r"(afr[mt][3]),
                          "r"(bfr[nt][0]), "r"(bfr[nt][1]));
                }
        }

        if (c < NCH - 1) STA(buf ^ 1);        // A reg->smem (after compute)
    }
#undef LDA
#undef STA
#undef LDB

    // ---- epilogue: write h (fp16), fused attdot ----
    float psrc[2][2], pdst[2][2];
#pragma unroll
    for (int mt = 0; mt < 2; mt++) {
        psrc[mt][0] = psrc[mt][1] = 0.f;
        pdst[mt][0] = pdst[mt][1] = 0.f;
    }

#pragma unroll
    for (int mt = 0; mt < 2; mt++) {
        int row0 = block_row + wm + mt * 16 + gid;
#pragma unroll
        for (int nt = 0; nt < 8; nt++) {
            int col = wn + nt * 8 + tig * 2;
            float s0 = __ldg(att_src + col), s1 = __ldg(att_src + col + 1);
            float d0 = __ldg(att_dst + col), d1 = __ldg(att_dst + col + 1);
            psrc[mt][0] += acc[mt][nt][0] * s0 + acc[mt][nt][1] * s1;
            pdst[mt][0] += acc[mt][nt][0] * d0 + acc[mt][nt][1] * d1;
            psrc[mt][1] += acc[mt][nt][2] * s0 + acc[mt][nt][3] * s1;
            pdst[mt][1] += acc[mt][nt][2] * d0 + acc[mt][nt][3] * d1;
            if (row0 < M) {
                __half2 hv = __floats2half2_rn(acc[mt][nt][0], acc[mt][nt][1]);
                *(__half2*)&g_hh[(size_t)row0 * HID + col] = hv;
            }
            if (row0 + 8 < M) {
                __half2 hv = __floats2half2_rn(acc[mt][nt][2], acc[mt][nt][3]);
                *(__half2*)&g_hh[(size_t)(row0 + 8) * HID + col] = hv;
            }
        }
    }

    // quad reduce (over tig lanes)
#pragma unroll
    for (int mt = 0; mt < 2; mt++)
#pragma unroll
        for (int hf = 0; hf < 2; hf++) {
            psrc[mt][hf] += __shfl_xor_sync(0xffffffffu, psrc[mt][hf], 1);
            psrc[mt][hf] += __shfl_xor_sync(0xffffffffu, psrc[mt][hf], 2);
            pdst[mt][hf] += __shfl_xor_sync(0xffffffffu, pdst[mt][hf], 1);
            pdst[mt][hf] += __shfl_xor_sync(0xffffffffu, pdst[mt][hf], 2);
        }

    __syncthreads();   // compute done everywhere; reuse smem for reduction
    float* rs = (float*)smem;          // [128][2]
    float* rd = (float*)smem + 256;    // [128][2]
    int nh = warp >> 2;
    if (tig == 0) {
#pragma unroll
        for (int mt = 0; mt < 2; mt++)
#pragma unroll
            for (int hf = 0; hf < 2; hf++) {
                int rl = wm + mt * 16 + gid + hf * 8;
                rs[rl * 2 + nh] = psrc[mt][hf];
                rd[rl * 2 + nh] = pdst[mt][hf];
            }
    }
    __syncthreads();
    if (tid < 128) {
        int r = block_row + tid;
        if (r < M) {
            g_asrc[r] = rs[tid * 2] + rs[tid * 2 + 1];
            g_adst[r] = rd[tid * 2] + rd[tid * 2 + 1];
        }
    }
}

// scan1: per-block (256 nodes) local exclusive scan of (cnt+1); block sums.
__global__ __launch_bounds__(256) void scan1_kernel(int N) {
    __shared__ int ws[8];
    int t = threadIdx.x, b = blockIdx.x;
    int i = b * 256 + t;
    int c = 0;
    if (i < N) { c = g_cnt[i] + 1; g_cnt[i] = 0; }   // +1 = self loop
    int lane = t & 31, w = t >> 5;
    int v = c;
#pragma unroll
    for (int o = 1; o < 32; o <<= 1) {
        int u = __shfl_up_sync(0xffffffffu, v, o);
        if (lane >= o) v += u;
    }
    if (lane == 31) ws[w] = v;
    __syncthreads();
    if (w == 0) {
        int x = (lane < 8) ? ws[lane] : 0;
#pragma unroll
        for (int o = 1; o < 8; o <<= 1) {
            int u = __shfl_up_sync(0xffffffffu, x, o);
            if (lane >= o) x += u;
        }
        if (lane < 8) ws[lane] = x;
    }
    __syncthreads();
    int excl = v - c + (w > 0 ? ws[w - 1] : 0);
    if (i < N) g_off[i] = excl;
    if (t == 255) g_bsum[b] = excl + c;
}

// scan23: each block reduces g_bsum itself (prefix + total), applies.
__global__ __launch_bounds__(256) void scan23_kernel(int nb, int N) {
    __shared__ int shp[8], sht[8];
    int t = threadIdx.x, b = blockIdx.x;
    int accp = 0, acct = 0;
    for (int i = t; i < nb; i += 256) {
        int v = g_bsum[i];
        acct += v;
        if (i < b) accp += v;
    }
    int lane = t & 31, w = t >> 5;
#pragma unroll
    for (int o = 16; o; o >>= 1) {
        accp += __shfl_xor_sync(0xffffffffu, accp, o);
        acct += __shfl_xor_sync(0xffffffffu, acct, o);
    }
    if (lane == 0) { shp[w] = accp; sht[w] = acct; }
    __syncthreads();
    if (t == 0) {
        int p = 0, tt = 0;
#pragma unroll
        for (int k = 0; k < 8; k++) { p += shp[k]; tt += sht[k]; }
        shp[0] = p; sht[0] = tt;
    }
    __syncthreads();
    int pre = shp[0];
    int i = b * 256 + t;
    if (i < N) {
        int o = g_off[i] + pre;
        g_off[i] = o;
        g_cur[i] = o;
    }
    if (b == nb - 1 && t == 0) g_off[N] = sht[0];
}

// scatter edges (and self loops) into CSR order.
__global__ void scatter_kernel(const int* __restrict__ ei, int E, int N) {
    int i = blockIdx.x * blockDim.x + threadIdx.x;
    int tot = E + N;
    if (i >= tot) return;
    int s, d;
    if (i < E) { s = ei[i]; d = ei[E + i]; }
    else       { s = d = i - E; }
    int pos = atomicAdd(&g_cur[d], 1);
    g_csr[pos] = s;
}

// fused GAT, single pass: warp per dst node. For each incoming edge, all lanes
// broadcast-load src + a_src[src], compute p = exp(leakyrelu(.)) redundantly
// (den identical in every lane -> no reduction), gather fp16 h row, accumulate
// p*h. Divide by den once, bias+relu, global max pool.
__global__ __launch_bounds__(256) void gat_kernel(const float* __restrict__ bias,
                                                  const int* __restrict__ batch,
                                                  float* pool, int N) {
    int node = (blockIdx.x * blockDim.x + threadIdx.x) >> 5;
    int lane = threadIdx.x & 31;
    if (node >= N) return;

    int base = g_off[node];
    int deg  = g_off[node + 1] - base;
    float adst = g_adst[node];

    const uint2* hh = (const uint2*)g_hh;   // 32 uint2 per row
    float4 A0 = make_float4(0.f, 0.f, 0.f, 0.f);
    float4 A1 = make_float4(0.f, 0.f, 0.f, 0.f);
    float den = 0.f;

#define GAT_P(s_, p_) do {                                                   \
    float e_ = g_asrc[s_] + adst;                                            \
    e_ = e_ > 0.f ? e_ : 0.2f * e_;                                          \
    p_ = __expf(e_);                                                         \
    den += p_;                                                               \
} while (0)
#define GAT_FMA0(p_, v_) do {                                                \
    float2 f_;                                                               \
    f_ = __half22float2(*(__half2*)&(v_).x);                                 \
    A0.x = fmaf(p_, f_.x, A0.x); A0.y = fmaf(p_, f_.y, A0.y);                \
    f_ = __half22float2(*(__half2*)&(v_).y);                                 \
    A0.z = fmaf(p_, f_.x, A0.z); A0.w = fmaf(p_, f_.y, A0.w);                \
} while (0)
#define GAT_FMA1(p_, v_) do {                                                \
    float2 f_;                                                               \
    f_ = __half22float2(*(__half2*)&(v_).x);                                 \
    A1.x = fmaf(p_, f_.x, A1.x); A1.y = fmaf(p_, f_.y, A1.y);                \
    f_ = __half22float2(*(__half2*)&(v_).y);                                 \
    A1.z = fmaf(p_, f_.x, A1.z); A1.w = fmaf(p_, f_.y, A1.w);                \
} while (0)

    int j = 0;
    for (; j + 4 <= deg; j += 4) {
        int s0 = g_csr[base + j],     s1 = g_csr[base + j + 1];
        int s2 = g_csr[base + j + 2], s3 = g_csr[base + j + 3];
        uint2 v0 = hh[(size_t)s0 * 32 + lane];
        uint2 v1 = hh[(size_t)s1 * 32 + lane];
        uint2 v2 = hh[(size_t)s2 * 32 + lane];
        uint2 v3 = hh[(size_t)s3 * 32 + lane];
        float p0, p1, p2, p3;
        GAT_P(s0, p0); GAT_P(s1, p1); GAT_P(s2, p2); GAT_P(s3, p3);
        GAT_FMA0(p0, v0); GAT_FMA1(p1, v1);
        GAT_FMA0(p2, v2); GAT_FMA1(p3, v3);
    }
    for (; j < deg; j++) {
        int s0 = g_csr[base + j];
        uint2 v0 = hh[(size_t)s0 * 32 + lane];
        float p0;
        GAT_P(s0, p0);
        GAT_FMA0(p0, v0);
    }
#undef GAT_P
#undef GAT_FMA0
#undef GAT_FMA1

    float inv = 1.f / den;
    float4 b = ((const float4*)bias)[lane];
    float4 v;
    v.x = fmaxf((A0.x + A1.x) * inv + b.x, 0.f);
    v.y = fmaxf((A0.y + A1.y) * inv + b.y, 0.f);
    v.z = fmaxf((A0.z + A1.z) * inv + b.z, 0.f);
    v.w = fmaxf((A0.w + A1.w) * inv + b.w, 0.f);

    int g = batch[node];
    int* p = (int*)(pool + (size_t)g * HID + lane * 4);
    // values >= 0 so signed-int compare is order-preserving
    atomicMax(p + 0, __float_as_int(v.x));
    atomicMax(p + 1, __float_as_int(v.y));
    atomicMax(p + 2, __float_as_int(v.z));
    atomicMax(p + 3, __float_as_int(v.w));
}

// ---------------- launch ----------------
extern "C" void kernel_launch(void* const* d_in, const int* in_sizes, int n_in,
                              void* d_out, int out_size) {
    const float* x       = (const float*)d_in[0];   // [N, 1024]
    const float* W       = (const float*)d_in[1];   // [1024, 128]
    const float* att_src = (const float*)d_in[2];   // [128]
    const float* att_dst = (const float*)d_in[3];   // [128]
    const float* bias    = (const float*)d_in[4];   // [128]
    const int*   ei      = (const int*)d_in[5];     // [2, E]
    const int*   batch   = (const int*)d_in[6];     // [N]
    float* pool = (float*)d_out;                    // [G, 128]

    const int N = in_sizes[0] / IN_DIM;
    const int E = in_sizes[5] / 2;
    const int tot = E + N;
    const int nb = (N + 255) / 256;

    // fork-join: full CSR branch (count -> scan -> scatter, stream s2) runs
    // concurrently with prepW + GEMM (main stream). Host-side objects only;
    // created per call, not destroyed (few calls total; destroying a
    // capture-participating stream mid-capture breaks the graph).
    cudaStream_t s2;
    cudaStreamCreateWithFlags(&s2, cudaStreamNonBlocking);
    cudaEvent_t e1, e2;
    cudaEventCreateWithFlags(&e1, cudaEventDisableTiming);
    cudaEventCreateWithFlags(&e2, cudaEventDisableTiming);

    // fork point (empty dependency — both branches start immediately)
    cudaEventRecord(e1, 0);
    cudaStreamWaitEvent(s2, e1, 0);

    // branch A (s2): edge count + CSR offsets + scatter
    count_kernel<<<(E + 255) / 256, 256, 0, s2>>>(ei, E);
    scan1_kernel<<<nb, 256, 0, s2>>>(N);
    scan23_kernel<<<nb, 256, 0, s2>>>(nb, N);
    scatter_kernel<<<(tot + 255) / 256, 256, 0, s2>>>(ei, E, N);
    cudaEventRecord(e2, s2);

    // branch B (main): W prep (small) then fp16 mma GEMM (+ fused attdot)
    prepW_kernel<<<(NCH * 2048 + 255) / 256, 256>>>(W, pool);
    gemm_f16_kernel<<<(N + 127) / 128, 256>>>(x, att_src, att_dst, N);

    // join, then fused softmax + aggregate + relu + pool (single edge pass)
    cudaStreamWaitEvent(0, e2, 0);
    gat_kernel<<<(N * 32 + 255) / 256, 256>>>(bias, batch, pool, N);
}

// round 16
// speedup vs baseline: 1.1610x; 1.1610x over previous
#include <cuda_runtime.h>
#include <cuda_fp16.h>
#include <math.h>
#include <stdint.h>

#define MAXN     50000
#define MAXE     1600000
#define IN_DIM   1024
#define HID      128
#define MAXG     64
#define MAXETOT  (MAXE + MAXN)

// fp16 mma GEMM config: 256 threads, 8 warps (2m x 4n), BM=64, BN=128, BK=32
#define NCH      (IN_DIM / 32)      // 32 chunks of k=32
#define A_ROWB   80                 // bytes per A smem row (64 used + 16 pad)
#define A_STG    (64 * A_ROWB)      // 5120 per stage
#define B_ROWB   80                 // bytes per B col-row (64 used + 16 pad)
#define B_STG    (128 * B_ROWB)     // 10240 per stage
#define SM_B0    (2 * A_STG)
#define SM_TOT   (2 * A_STG + 2 * B_STG)   // 30720 bytes

// ---------------- device scratch (static; no allocations) ----------------
__device__ __half g_hh[(size_t)MAXN * HID];   // h in fp16 (gather copy)
__device__ __half2 g_Wp2[NCH * 2048];         // W col-major per chunk: [ch][n][kpair]
__device__ int2   g_ps[MAXETOT];              // per-edge {p bits, src id}, CSR order
__device__ float  g_asrc[MAXN];
__device__ float  g_adst[MAXN];
__device__ int    g_cnt[MAXN];                // per-dst in-degree (re-zeroed by scan1)
__device__ int    g_off[MAXN + 1];            // CSR offsets
__device__ int    g_cur[MAXN];                // scatter cursors
__device__ int    g_bsum[256];                // scan block sums

// ---------------- kernels ----------------

// prepW: pool=0 + W -> half2, col-major per chunk: [ch][n][kpair 0..15].
__global__ void prepW_kernel(const float* __restrict__ W, float* pool) {
    int i = blockIdx.x * blockDim.x + threadIdx.x;
    if (i < MAXG * HID) pool[i] = 0.f;
    if (i < NCH * 2048) {
        int kp = i & 15;
        int n  = (i >> 4) & 127;
        int ch = i >> 11;
        int k0 = ch * 32 + kp * 2;
        g_Wp2[i] = __floats2half2_rn(W[(size_t)k0 * HID + n],
                                     W[(size_t)(k0 + 1) * HID + n]);
    }
}

// count: per-dst edge count (independent of W; runs on the CSR branch).
__global__ void count_kernel(const int* __restrict__ ei, int E) {
    int i = blockIdx.x * blockDim.x + threadIdx.x;
    if (i < E) atomicAdd(&g_cnt[ei[E + i]], 1);
}

#define LDSM_X4(r0_, r1_, r2_, r3_, addr_) \
    asm volatile("ldmatrix.sync.aligned.m8n8.x4.shared.b16 {%0,%1,%2,%3}, [%4];" \
                 : "=r"(r0_), "=r"(r1_), "=r"(r2_), "=r"(r3_) : "r"(addr_))

// fp16 mma.sync m16n8k16 GEMM, BM=64 tiles (grid 2x finer -> tail wave cost
// halves at >=3 blocks/SM). 8 warps: warp&1 = m half (32 rows), warp>>1 = n
// quarter (32 cols). Fused attdot epilogue; h written fp16.
__global__ __launch_bounds__(256, 3) void gemm_f16_kernel(
        const float* __restrict__ A,
        const float* __restrict__ att_src,
        const float* __restrict__ att_dst, int M) {
    __shared__ char smem[SM_TOT];
    const uint32_t sbase = (uint32_t)__cvta_generic_to_shared(smem);

    const int tid  = threadIdx.x;
    const int lane = tid & 31;
    const int warp = tid >> 5;
    const int gid  = lane >> 2;   // 0..7
    const int tig  = lane & 3;    // 0..3
    const int wm   = (warp & 1) * 32;
    const int wn   = (warp >> 1) * 32;
    const int block_row = blockIdx.x * 64;

    // ldmatrix per-lane base addresses.
    // A (mt): row = wm + mt*16 + (lane&7) + 8*bit3(lane); +16B on bit4 (k half)
    uint32_t aLm[2];
#pragma unroll
    for (int mt = 0; mt < 2; mt++) {
        int row = wm + mt * 16 + (lane & 7) + (((lane >> 3) & 1) << 3);
        aLm[mt] = sbase + row * A_ROWB + (((lane >> 4) & 1) << 4);
    }
    // B (ntp covers nt=2*ntp, 2*ntp+1): col-row = wn + ntp*16 + (lane&7) + 8*bit4;
    // +16B on bit3 (k half)
    uint32_t bLm[2];
#pragma unroll
    for (int ntp = 0; ntp < 2; ntp++) {
        int col = wn + ntp * 16 + (lane & 7) + (((lane >> 4) & 1) << 3);
        bLm[ntp] = sbase + SM_B0 + col * B_ROWB + (((lane >> 3) & 1) << 4);
    }

    // A LDG mapping: iter i (i<2): row = i*32 + (tid>>3), cols (tid&7)*4
    const int ar = tid >> 3;   // 0..31
    const int aq = tid & 7;    // 0..7
    bool avalid[2];
    const float* aptr[2];
#pragma unroll
    for (int i = 0; i < 2; i++) {
        int gr = block_row + i * 32 + ar;
        avalid[i] = gr < M;
        aptr[i] = A + (size_t)(avalid[i] ? gr : 0) * IN_DIM + aq * 4;
    }

    float4 areg[2];
#define LDA(c_) do {                                                         \
    _Pragma("unroll")                                                        \
    for (int i = 0; i < 2; i++)                                              \
        areg[i] = avalid[i] ? *(const float4*)(aptr[i] + (c_) * 32)          \
                            : make_float4(0.f, 0.f, 0.f, 0.f);               \
} while (0)
#define STA(buf_) do {                                                       \
    _Pragma("unroll")                                                        \
    for (int i = 0; i < 2; i++) {                                            \
        __half2 h0 = __floats2half2_rn(areg[i].x, areg[i].y);                \
        __half2 h1 = __floats2half2_rn(areg[i].z, areg[i].w);                \
        uint2 u; u.x = *(uint32_t*)&h0; u.y = *(uint32_t*)&h1;               \
        *(uint2*)(smem + (buf_) * A_STG + (i * 32 + ar) * A_ROWB + aq * 8) = u; \
    }                                                                        \
} while (0)
// B tile: 512 16B segs; seg q -> col q>>2, seg-in-col q&3; src contiguous.
#define LDB(c_, buf_) do {                                                   \
    _Pragma("unroll")                                                        \
    for (int j = 0; j < 2; j++) {                                            \
        int q = j * 256 + tid;                                               \
        const __half2* src = g_Wp2 + (size_t)(c_) * 2048 + q * 4;            \
        uint32_t dst = sbase + SM_B0 + (buf_) * B_STG +                      \
                       (q >> 2) * B_ROWB + (q & 3) * 16;                     \
        asm volatile("cp.async.cg.shared.global [%0], [%1], 16;"             \
                     :: "r"(dst), "l"(src));                                 \
    }                                                                        \
    asm volatile("cp.async.commit_group;");                                  \
} while (0)

    float acc[2][4][4];
#pragma unroll
    for (int mt = 0; mt < 2; mt++)
#pragma unroll
        for (int nt = 0; nt < 4; nt++)
#pragma unroll
            for (int i = 0; i < 4; i++) acc[mt][nt][i] = 0.f;

    // prologue
    LDA(0); STA(0); LDB(0, 0);

#pragma unroll 1
    for (int c = 0; c < NCH; c++) {
        const int buf = c & 1;
        if (c < NCH - 1) LDA(c + 1);          // A global->reg prefetch
        asm volatile("cp.async.wait_group 0;");   // B(c) ready
        __syncthreads();
        if (c < NCH - 1) LDB(c + 1, buf ^ 1); // hide B latency under compute

        const uint32_t aOff = buf * A_STG;
        const uint32_t bOff = buf * B_STG;
#pragma unroll
        for (int ks = 0; ks < 2; ks++) {
            uint32_t afr[2][4];
#pragma unroll
            for (int mt = 0; mt < 2; mt++)
                LDSM_X4(afr[mt][0], afr[mt][1], afr[mt][2], afr[mt][3],
                        aLm[mt] + aOff + ks * 32);
            uint32_t bfr[4][2];
#pragma unroll
            for (int ntp = 0; ntp < 2; ntp++)
                LDSM_X4(bfr[2 * ntp][0], bfr[2 * ntp][1],
                        bfr[2 * ntp + 1][0], bfr[2 * ntp + 1][1],
                        bLm[ntp] + bOff + ks * 32);
#pragma unroll
            for (int mt = 0; mt < 2; mt++)
#pragma unroll
                for (int nt = 0; nt < 4; nt++) {
                    asm("mma.sync.aligned.m16n8k16.row.col.f32.f16.f16.f32 "
                        "{%0,%1,%2,%3}, {%4,%5,%6,%7}, {%8,%9}, {%0,%1,%2,%3};"
                        : "+f"(acc[mt][nt][0]), "+f"(acc[mt][nt][1]),
                          "+f"(acc[mt][nt][2]), "+f"(acc[mt][nt][3])
                        : "r"(afr[mt][0]), "r"(afr[mt][1]),
                          "r"(afr[mt][2]), "r"(afr[mt][3]),
                          "r"(bfr[nt][0]), "r"(bfr[nt][1]));
                }
        }

        if (c < NCH - 1) STA(buf ^ 1);        // A reg->smem (after compute)
    }
#undef LDA
#undef STA
#undef LDB

    // ---- epilogue: write h (fp16), fused attdot ----
    float psrc[2][2], pdst[2][2];
#pragma unroll
    for (int mt = 0; mt < 2; mt++) {
        psrc[mt][0] = psrc[mt][1] = 0.f;
        pdst[mt][0] = pdst[mt][1] = 0.f;
    }

#pragma unroll
    for (int mt = 0; mt < 2; mt++) {
        int row0 = block_row + wm + mt * 16 + gid;
#pragma unroll
        for (int nt = 0; nt < 4; nt++) {
            int col = wn + nt * 8 + tig * 2;
            float s0 = __ldg(att_src + col), s1 = __ldg(att_src + col + 1);
            float d0 = __ldg(att_dst + col), d1 = __ldg(att_dst + col + 1);
            psrc[mt][0] += acc[mt][nt][0] * s0 + acc[mt][nt][1] * s1;
            pdst[mt][0] += acc[mt][nt][0] * d0 + acc[mt][nt][1] * d1;
            psrc[mt][1] += acc[mt][nt][2] * s0 + acc[mt][nt][3] * s1;
            pdst[mt][1] += acc[mt][nt][2] * d0 + acc[mt][nt][3] * d1;
            if (row0 < M) {
                __half2 hv = __floats2half2_rn(acc[mt][nt][0], acc[mt][nt][1]);
                *(__half2*)&g_hh[(size_t)row0 * HID + col] = hv;
            }
            if (row0 + 8 < M) {
                __half2 hv = __floats2half2_rn(acc[mt][nt][2], acc[mt][nt][3]);
                *(__half2*)&g_hh[(size_t)(row0 + 8) * HID + col] = hv;
            }
        }
    }

    // quad reduce (over tig lanes): lane tig==0 holds row-sum of its 32 cols
#pragma unroll
    for (int mt = 0; mt < 2; mt++)
#pragma unroll
        for (int hf = 0; hf < 2; hf++) {
            psrc[mt][hf] += __shfl_xor_sync(0xffffffffu, psrc[mt][hf], 1);
            psrc[mt][hf] += __shfl_xor_sync(0xffffffffu, psrc[mt][hf], 2);
            pdst[mt][hf] += __shfl_xor_sync(0xffffffffu, pdst[mt][hf], 1);
            pdst[mt][hf] += __shfl_xor_sync(0xffffffffu, pdst[mt][hf], 2);
        }

    __syncthreads();   // compute done everywhere; reuse smem for reduction
    float* rs = (float*)smem;          // [64][4]
    float* rd = (float*)smem + 256;    // [64][4]
    int nq = warp >> 1;                // n quarter 0..3
    if (tig == 0) {
#pragma unroll
        for (int mt = 0; mt < 2; mt++)
#pragma unroll
            for (int hf = 0; hf < 2; hf++) {
                int rl = wm + mt * 16 + gid + hf * 8;
                rs[rl * 4 + nq] = psrc[mt][hf];
                rd[rl * 4 + nq] = pdst[mt][hf];
            }
    }
    __syncthreads();
    if (tid < 64) {
        int r = block_row + tid;
        if (r < M) {
            g_asrc[r] = rs[tid * 4] + rs[tid * 4 + 1] + rs[tid * 4 + 2] + rs[tid * 4 + 3];
            g_adst[r] = rd[tid * 4] + rd[tid * 4 + 1] + rd[tid * 4 + 2] + rd[tid * 4 + 3];
        }
    }
}

// scan1: per-block (256 nodes) local exclusive scan of (cnt+1); block sums.
__global__ __launch_bounds__(256) void scan1_kernel(int N) {
    __shared__ int ws[8];
    int t = threadIdx.x, b = blockIdx.x;
    int i = b * 256 + t;
    int c = 0;
    if (i < N) { c = g_cnt[i] + 1; g_cnt[i] = 0; }   // +1 = self loop
    int lane = t & 31, w = t >> 5;
    int v = c;
#pragma unroll
    for (int o = 1; o < 32; o <<= 1) {
        int u = __shfl_up_sync(0xffffffffu, v, o);
        if (lane >= o) v += u;
    }
    if (lane == 31) ws[w] = v;
    __syncthreads();
    if (w == 0) {
        int x = (lane < 8) ? ws[lane] : 0;
#pragma unroll
        for (int o = 1; o < 8; o <<= 1) {
            int u = __shfl_up_sync(0xffffffffu, x, o);
            if (lane >= o) x += u;
        }
        if (lane < 8) ws[lane] = x;
    }
    __syncthreads();
    int excl = v - c + (w > 0 ? ws[w - 1] : 0);
    if (i < N) g_off[i] = excl;
    if (t == 255) g_bsum[b] = excl + c;
}

// scan23: each block reduces g_bsum itself (prefix + total), applies.
__global__ __launch_bounds__(256) void scan23_kernel(int nb, int N) {
    __shared__ int shp[8], sht[8];
    int t = threadIdx.x, b = blockIdx.x;
    int accp = 0, acct = 0;
    for (int i = t; i < nb; i += 256) {
        int v = g_bsum[i];
        acct += v;
        if (i < b) accp += v;
    }
    int lane = t & 31, w = t >> 5;
#pragma unroll
    for (int o = 16; o; o >>= 1) {
        accp += __shfl_xor_sync(0xffffffffu, accp, o);
        acct += __shfl_xor_sync(0xffffffffu, acct, o);
    }
    if (lane == 0) { shp[w] = accp; sht[w] = acct; }
    __syncthreads();
    if (t == 0) {
        int p = 0, tt = 0;
#pragma unroll
        for (int k = 0; k < 8; k++) { p += shp[k]; tt += sht[k]; }
        shp[0] = p; sht[0] = tt;
    }
    __syncthreads();
    int pre = shp[0];
    int i = b * 256 + t;
    if (i < N) {
        int o = g_off[i] + pre;
        g_off[i] = o;
        g_cur[i] = o;
    }
    if (b == nb - 1 && t == 0) g_off[N] = sht[0];
}

// scatter edges (and self loops) into CSR order: src into g_ps[.].y
__global__ void scatter_kernel(const int* __restrict__ ei, int E, int N) {
    int i = blockIdx.x * blockDim.x + threadIdx.x;
    int tot = E + N;
    if (i >= tot) return;
    int s, d;
    if (i < E) { s = ei[i]; d = ei[E + i]; }
    else       { s = d = i - E; }
    int pos = atomicAdd(&g_cur[d], 1);
    g_ps[pos].y = s;
}

// fused GAT (two-pass): warp per dst node. Pass 1: p=exp(leakyrelu(e)) (no max
// shift — e bounded), store p, warp-sum den. Pass 2: gather fp16 h, acc p*h.
__global__ __launch_bounds__(256) void gat_kernel(const float* __restrict__ bias,
                                                  const int* __restrict__ batch,
                                                  float* pool, int N) {
    int node = (blockIdx.x * blockDim.x + threadIdx.x) >> 5;
    int lane = threadIdx.x & 31;
    if (node >= N) return;

    int base = g_off[node];
    int deg  = g_off[node + 1] - base;
    float adst = g_adst[node];

    float den = 0.f;
    for (int j = lane; j < deg; j += 32) {
        int s = g_ps[base + j].y;
        float e = g_asrc[s] + adst;
        e = e > 0.f ? e : 0.2f * e;
        float p = __expf(e);
        g_ps[base + j].x = __float_as_int(p);
        den += p;
    }
#pragma unroll
    for (int o = 16; o; o >>= 1)
        den += __shfl_xor_sync(0xffffffffu, den, o);

    const uint2* hh = (const uint2*)g_hh;   // 32 uint2 per row
    const int2* ps = g_ps;
    float4 A0 = make_float4(0.f, 0.f, 0.f, 0.f);
    float4 A1 = make_float4(0.f, 0.f, 0.f, 0.f);
    int j = 0;
    for (; j + 4 <= deg; j += 4) {
        int2 e0 = ps[base + j],     e1 = ps[base + j + 1];
        int2 e2 = ps[base + j + 2], e3 = ps[base + j + 3];
        float p0 = __int_as_float(e0.x), p1 = __int_as_float(e1.x);
        float p2 = __int_as_float(e2.x), p3 = __int_as_float(e3.x);
        uint2 v0 = hh[(size_t)e0.y * 32 + lane];
        uint2 v1 = hh[(size_t)e1.y * 32 + lane];
        uint2 v2 = hh[(size_t)e2.y * 32 + lane];
        uint2 v3 = hh[(size_t)e3.y * 32 + lane];
        float2 f;
        f = __half22float2(*(__half2*)&v0.x); A0.x = fmaf(p0, f.x, A0.x); A0.y = fmaf(p0, f.y, A0.y);
        f = __half22float2(*(__half2*)&v0.y); A0.z = fmaf(p0, f.x, A0.z); A0.w = fmaf(p0, f.y, A0.w);
        f = __half22float2(*(__half2*)&v1.x); A1.x = fmaf(p1, f.x, A1.x); A1.y = fmaf(p1, f.y, A1.y);
        f = __half22float2(*(__half2*)&v1.y); A1.z = fmaf(p1, f.x, A1.z); A1.w = fmaf(p1, f.y, A1.w);
        f = __half22float2(*(__half2*)&v2.x); A0.x = fmaf(p2, f.x, A0.x); A0.y = fmaf(p2, f.y, A0.y);
        f = __half22float2(*(__half2*)&v2.y); A0.z = fmaf(p2, f.x, A0.z); A0.w = fmaf(p2, f.y, A0.w);
        f = __half22float2(*(__half2*)&v3.x); A1.x = fmaf(p3, f.x, A1.x); A1.y = fmaf(p3, f.y, A1.y);
        f = __half22float2(*(__half2*)&v3.y); A1.z = fmaf(p3, f.x, A1.z); A1.w = fmaf(p3, f.y, A1.w);
    }
    for (; j < deg; j++) {
        int2 e0 = ps[base + j];
        float p0 = __int_as_float(e0.x);
        uint2 v0 = hh[(size_t)e0.y * 32 + lane];
        float2 f;
        f = __half22float2(*(__half2*)&v0.x); A0.x = fmaf(p0, f.x, A0.x); A0.y = fmaf(p0, f.y, A0.y);
        f = __half22float2(*(__half2*)&v0.y); A0.z = fmaf(p0, f.x, A0.z); A0.w = fmaf(p0, f.y, A0.w);
    }

    float inv = 1.f / den;
    float4 b = ((const float4*)bias)[lane];
    float4 v;
    v.x = fmaxf((A0.x + A1.x) * inv + b.x, 0.f);
    v.y = fmaxf((A0.y + A1.y) * inv + b.y, 0.f);
    v.z = fmaxf((A0.z + A1.z) * inv + b.z, 0.f);
    v.w = fmaxf((A0.w + A1.w) * inv + b.w, 0.f);

    int g = batch[node];
    int* p = (int*)(pool + (size_t)g * HID + lane * 4);
    // values >= 0 so signed-int compare is order-preserving
    atomicMax(p + 0, __float_as_int(v.x));
    atomicMax(p + 1, __float_as_int(v.y));
    atomicMax(p + 2, __float_as_int(v.z));
    atomicMax(p + 3, __float_as_int(v.w));
}

// ---------------- launch ----------------
extern "C" void kernel_launch(void* const* d_in, const int* in_sizes, int n_in,
                              void* d_out, int out_size) {
    const float* x       = (const float*)d_in[0];   // [N, 1024]
    const float* W       = (const float*)d_in[1];   // [1024, 128]
    const float* att_src = (const float*)d_in[2];   // [128]
    const float* att_dst = (const float*)d_in[3];   // [128]
    const float* bias    = (const float*)d_in[4];   // [128]
    const int*   ei      = (const int*)d_in[5];     // [2, E]
    const int*   batch   = (const int*)d_in[6];     // [N]
    float* pool = (float*)d_out;                    // [G, 128]

    const int N = in_sizes[0] / IN_DIM;
    const int E = in_sizes[5] / 2;
    const int tot = E + N;
    const int nb = (N + 255) / 256;

    // fork-join: full CSR branch (count -> scan -> scatter, stream s2) runs
    // concurrently with prepW + GEMM (main stream). Host-side objects only;
    // created per call, not destroyed (few calls total; destroying a
    // capture-participating stream mid-capture breaks the graph).
    cudaStream_t s2;
    cudaStreamCreateWithFlags(&s2, cudaStreamNonBlocking);
    cudaEvent_t e1, e2;
    cudaEventCreateWithFlags(&e1, cudaEventDisableTiming);
    cudaEventCreateWithFlags(&e2, cudaEventDisableTiming);

    // fork point (empty dependency — both branches start immediately)
    cudaEventRecord(e1, 0);
    cudaStreamWaitEvent(s2, e1, 0);

    // branch A (s2): edge count + CSR offsets + scatter
    count_kernel<<<(E + 255) / 256, 256, 0, s2>>>(ei, E);
    scan1_kernel<<<nb, 256, 0, s2>>>(N);
    scan23_kernel<<<nb, 256, 0, s2>>>(nb, N);
    scatter_kernel<<<(tot + 255) / 256, 256, 0, s2>>>(ei, E, N);
    cudaEventRecord(e2, s2);

    // branch B (main): W prep (small) then fp16 mma GEMM (+ fused attdot)
    prepW_kernel<<<(NCH * 2048 + 255) / 256, 256>>>(W, pool);
    gemm_f16_kernel<<<(N + 63) / 64, 256>>>(x, att_src, att_dst, N);

    // join, then fused softmax + aggregate + relu + pool
    cudaStreamWaitEvent(0, e2, 0);
    gat_kernel<<<(N * 32 + 255) / 256, 256>>>(bias, batch, pool, N);
}